// round 2
// baseline (speedup 1.0000x reference)
#include <cuda_runtime.h>
#include <math.h>

// Problem constants (fixed shapes per reference)
#define NN 100000          // nodes
#define NE 1600000         // edges
#define DIN 128
#define DHID 32
#define NEG_SLOPE 0.2f

// ---------------- device scratch (static allocation, allowed) ----------------
__device__ int   g_deg[NN];
__device__ int   g_cursor[NN];
__device__ int   g_rowptr[NN + 1];
__device__ int   g_bsums[128];
__device__ int   g_csr_src[NE];
__device__ int   g_is64;           // 1 if edge_index is int64, 0 if int32
__device__ float g_xl[NN * DHID];
__device__ float g_xr[NN * DHID];
__device__ float g_h[NN * DHID];

// ---------------- edge dtype detection ----------------
// int64 values < 2^31 => every odd 32-bit word is 0. int32 data: essentially
// impossible for 2048 sampled odd words to all be zero.
__global__ void detect_dtype_k(const unsigned int* __restrict__ w) {
    __shared__ int allz;
    if (threadIdx.x == 0) allz = 1;
    __syncthreads();
    for (int i = threadIdx.x; i < 2048; i += blockDim.x) {
        if (w[2 * i + 1] != 0u) allz = 0;
    }
    __syncthreads();
    if (threadIdx.x == 0) g_is64 = allz;
}

__device__ __forceinline__ int load_edge(const void* ei, long long idx, int is64) {
    if (is64) return (int)((const long long*)ei)[idx];
    return ((const int*)ei)[idx];
}

// ---------------- CSR build ----------------
__global__ void zero_counts_k() {
    int i = blockIdx.x * blockDim.x + threadIdx.x;
    if (i < NN) { g_deg[i] = 0; g_cursor[i] = 0; }
}

__global__ void hist_k(const void* __restrict__ ei) {
    int e = blockIdx.x * blockDim.x + threadIdx.x;
    if (e >= NE) return;
    int is64 = g_is64;
    int dst = load_edge(ei, (long long)NE + e, is64);
    atomicAdd(&g_deg[dst], 1);
}

__global__ void scan_local_k() {            // grid: ceil(NN/1024), block: 1024
    __shared__ int sm[1024];
    int tid = threadIdx.x;
    int i = blockIdx.x * 1024 + tid;
    int v = (i < NN) ? g_deg[i] : 0;
    sm[tid] = v;
    __syncthreads();
    #pragma unroll
    for (int off = 1; off < 1024; off <<= 1) {
        int t = (tid >= off) ? sm[tid - off] : 0;
        __syncthreads();
        sm[tid] += t;
        __syncthreads();
    }
    if (i < NN) g_rowptr[i] = sm[tid] - v;      // exclusive
    if (tid == 1023) g_bsums[blockIdx.x] = sm[1023];
}

__global__ void scan_bsums_k(int nb) {      // 1 block, 128 threads
    __shared__ int sm[128];
    int tid = threadIdx.x;
    int v = (tid < nb) ? g_bsums[tid] : 0;
    sm[tid] = v;
    __syncthreads();
    #pragma unroll
    for (int off = 1; off < 128; off <<= 1) {
        int t = (tid >= off) ? sm[tid - off] : 0;
        __syncthreads();
        sm[tid] += t;
        __syncthreads();
    }
    if (tid < nb) g_bsums[tid] = sm[tid] - v;   // exclusive
}

__global__ void add_offsets_k() {
    int i = blockIdx.x * blockDim.x + threadIdx.x;
    if (i < NN) g_rowptr[i] += g_bsums[i >> 10];
    if (i == 0) g_rowptr[NN] = NE;
}

__global__ void scatter_k(const void* __restrict__ ei) {
    int e = blockIdx.x * blockDim.x + threadIdx.x;
    if (e >= NE) return;
    int is64 = g_is64;
    int src = load_edge(ei, e, is64);
    int dst = load_edge(ei, (long long)NE + e, is64);
    int pos = g_rowptr[dst] + atomicAdd(&g_cursor[dst], 1);
    g_csr_src[pos] = src;
}

// ---------------- dual GEMM: OL = X @ Wl, OR = X @ Wr  (X: [NN,K], W: [K,32]) --
template <int K>
__global__ void gemm_dual_k(const float* __restrict__ X,
                            const float* __restrict__ Wl,
                            const float* __restrict__ Wr,
                            float* __restrict__ OL,
                            float* __restrict__ ORr) {
    constexpr int TN = 64;                  // nodes per block
    extern __shared__ float smem[];
    float* s_x  = smem;                     // TN*K
    float* s_wl = smem + TN * K;            // K*32
    float* s_wr = s_wl + K * 32;            // K*32

    int tid = threadIdx.x;                  // 256 threads
    for (int idx = tid; idx < K * 32; idx += 256) {
        s_wl[idx] = Wl[idx];
        s_wr[idx] = Wr[idx];
    }
    int nb = blockIdx.x * TN;
    const float4* X4 = reinterpret_cast<const float4*>(X);
    float4* sx4 = reinterpret_cast<float4*>(s_x);
    int base4 = nb * (K / 4);
    int lim4 = NN * (K / 4) - base4;        // valid float4s left in X
    for (int idx = tid; idx < TN * (K / 4); idx += 256) {
        sx4[idx] = (idx < lim4) ? X4[base4 + idx] : make_float4(0.f, 0.f, 0.f, 0.f);
    }
    __syncthreads();

    int w = tid >> 5, lane = tid & 31;
    float aL[8], aR[8];
    #pragma unroll
    for (int j = 0; j < 8; j++) { aL[j] = 0.f; aR[j] = 0.f; }
    const float* xrow = &s_x[(w * 8) * K];

    for (int i = 0; i < K; i += 4) {
        float wl0 = s_wl[(i + 0) * 32 + lane];
        float wl1 = s_wl[(i + 1) * 32 + lane];
        float wl2 = s_wl[(i + 2) * 32 + lane];
        float wl3 = s_wl[(i + 3) * 32 + lane];
        float wr0 = s_wr[(i + 0) * 32 + lane];
        float wr1 = s_wr[(i + 1) * 32 + lane];
        float wr2 = s_wr[(i + 2) * 32 + lane];
        float wr3 = s_wr[(i + 3) * 32 + lane];
        #pragma unroll
        for (int j = 0; j < 8; j++) {
            float4 xv = *reinterpret_cast<const float4*>(&xrow[j * K + i]);
            aL[j] = fmaf(xv.x, wl0, aL[j]);
            aL[j] = fmaf(xv.y, wl1, aL[j]);
            aL[j] = fmaf(xv.z, wl2, aL[j]);
            aL[j] = fmaf(xv.w, wl3, aL[j]);
            aR[j] = fmaf(xv.x, wr0, aR[j]);
            aR[j] = fmaf(xv.y, wr1, aR[j]);
            aR[j] = fmaf(xv.z, wr2, aR[j]);
            aR[j] = fmaf(xv.w, wr3, aR[j]);
        }
    }
    #pragma unroll
    for (int j = 0; j < 8; j++) {
        int node = nb + w * 8 + j;
        if (node < NN) {
            OL[node * 32 + lane]  = aL[j];
            ORr[node * 32 + lane] = aR[j];
        }
    }
}

// ---------------- GATv2 edge pass: warp = dst node, lane = feature -----------
// Online softmax: single pass over incoming edges, no atomics.
template <bool RELU>
__global__ void gat_edge_k(const float* __restrict__ xl,
                           const float* __restrict__ xr,
                           const float* __restrict__ att,
                           const float* __restrict__ bias,
                           float* __restrict__ out) {
    int gw = (blockIdx.x * blockDim.x + threadIdx.x) >> 5;
    int lane = threadIdx.x & 31;
    if (gw >= NN) return;
    int n = gw;

    float xrk = xr[n * 32 + lane];
    float ak  = att[lane];
    int e0 = g_rowptr[n], e1 = g_rowptr[n + 1];

    float m = __int_as_float(0xff800000);   // -inf
    float ssum = 0.f, acc = 0.f;

    for (int e = e0; e < e1; e++) {
        int src = g_csr_src[e];
        float xlk = __ldg(&xl[src * 32 + lane]);
        float hk = xlk + xrk;
        float lr = hk > 0.f ? hk : NEG_SLOPE * hk;
        float p = lr * ak;
        #pragma unroll
        for (int off = 16; off > 0; off >>= 1)
            p += __shfl_xor_sync(0xffffffffu, p, off);
        float mn = fmaxf(m, p);
        float w0 = __expf(m - mn);          // exp(-inf)=0 on first edge
        float w1 = __expf(p - mn);
        ssum = ssum * w0 + w1;
        acc  = acc * w0 + w1 * xlk;
        m = mn;
    }

    float o = acc / (ssum + 1e-16f) + bias[lane];
    if (RELU) o = fmaxf(o, 0.f);
    out[n * 32 + lane] = o;
}

// ---------------- launch ----------------
extern "C" void kernel_launch(void* const* d_in, const int* in_sizes, int n_in,
                              void* d_out, int out_size) {
    const float* x    = (const float*)d_in[0];
    const void*  ei   = d_in[1];
    const float* W1l  = (const float*)d_in[2];
    const float* W1r  = (const float*)d_in[3];
    const float* att1 = (const float*)d_in[4];
    const float* b1   = (const float*)d_in[5];
    const float* W2l  = (const float*)d_in[6];
    const float* W2r  = (const float*)d_in[7];
    const float* att2 = (const float*)d_in[8];
    const float* b2   = (const float*)d_in[9];
    float* out = (float*)d_out;

    float *p_xl, *p_xr, *p_h;
    cudaGetSymbolAddress((void**)&p_xl, g_xl);
    cudaGetSymbolAddress((void**)&p_xr, g_xr);
    cudaGetSymbolAddress((void**)&p_h,  g_h);

    cudaFuncSetAttribute(gemm_dual_k<128>,
                         cudaFuncAttributeMaxDynamicSharedMemorySize, 65536);
    cudaFuncSetAttribute(gemm_dual_k<32>,
                         cudaFuncAttributeMaxDynamicSharedMemorySize, 16384);

    const int nscan = (NN + 1023) / 1024;   // 98

    // CSR build
    detect_dtype_k<<<1, 256>>>((const unsigned int*)ei);
    zero_counts_k<<<(NN + 255) / 256, 256>>>();
    hist_k<<<(NE + 255) / 256, 256>>>(ei);
    scan_local_k<<<nscan, 1024>>>();
    scan_bsums_k<<<1, 128>>>(nscan);
    add_offsets_k<<<(NN + 255) / 256, 256>>>();
    scatter_k<<<(NE + 255) / 256, 256>>>(ei);

    // Layer 1
    gemm_dual_k<128><<<(NN + 63) / 64, 256, 65536>>>(x, W1l, W1r, p_xl, p_xr);
    gat_edge_k<true><<<(NN * 32 + 255) / 256, 256>>>(p_xl, p_xr, att1, b1, p_h);

    // Layer 2
    gemm_dual_k<32><<<(NN + 63) / 64, 256, 16384>>>(p_h, W2l, W2r, p_xl, p_xr);
    gat_edge_k<false><<<(NN * 32 + 255) / 256, 256>>>(p_xl, p_xr, att2, b2, out);
}